// round 6
// baseline (speedup 1.0000x reference)
#include <cuda_runtime.h>

// VectorQuantizer: z [B,64] f32, codebook [1024,64] f32
// out = concat( z_q_st [B*64], vq_loss [1], indices-as-float [B] )

typedef unsigned long long u64;

#define K_CODES 1024
#define D 64
#define NPAIR (D/2)            // 32 dim-pairs
#define THREADS 256
#define ROWS_CTA 128
#define CHUNK 256              // codes staged per pass
#define NCHUNK (K_CODES/CHUNK)
#define TR 4                   // rows per thread
#define TC 8                   // codes per thread (per subtile)
#define ZP_STRIDE 130          // u64 stride, padded
#define CP_STRIDE 258          // u64 stride, padded

__device__ double   g_loss;
__device__ unsigned g_done;
__device__ float    g_c2[K_CODES];

static __device__ __forceinline__ u64 pack2(float x, float y) {
    u64 r; asm("mov.b64 %0,{%1,%2};" : "=l"(r) : "f"(x), "f"(y)); return r;
}
static __device__ __forceinline__ void unpack2(u64 v, float& x, float& y) {
    asm("mov.b64 {%0,%1},%2;" : "=f"(x), "=f"(y) : "l"(v));
}
static __device__ __forceinline__ u64 ffma2(u64 a, u64 b, u64 c) {
    u64 d; asm("fma.rn.f32x2 %0,%1,%2,%3;" : "=l"(d) : "l"(a), "l"(b), "l"(c)); return d;
}

// Prep: c2 per code (pairwise tree, unchanged), zero loss + done counter.
__global__ void vq_prep(const float* __restrict__ cb) {
    __shared__ float s[D];
    int k = blockIdx.x, d = threadIdx.x;
    float v = cb[k * D + d];
    s[d] = v * v;
    __syncthreads();
#pragma unroll
    for (int off = D / 2; off >= 1; off >>= 1) {
        if (d < off) s[d] = s[d] + s[d + off];
        __syncthreads();
    }
    if (d == 0) {
        g_c2[k] = s[0];
        if (k == 0) { g_loss = 0.0; g_done = 0u; }
    }
}

__global__ void __launch_bounds__(THREADS, 2)
vq_main(const float* __restrict__ z, const float* __restrict__ cb,
        float* __restrict__ out, int B, int out_size) {
    extern __shared__ char smraw[];
    u64*   s_zp = (u64*)smraw;                           // [NPAIR][ZP_STRIDE]
    u64*   s_cp = s_zp + NPAIR * ZP_STRIDE;              // [NPAIR][CP_STRIDE]
    float* s_c2 = (float*)(s_cp + NPAIR * CP_STRIDE);    // [1024]
    float* s_z2 = s_c2 + K_CODES;                        // [128]
    // overlays (used after mainloop, inside s_cp region which is large enough):
    float* candv = (float*)s_cp;                         // [128][8]
    int*   candi = (int*)(candv + ROWS_CTA * 8);         // [128][8]
    double* sd   = (double*)(candi + ROWS_CTA * 8 + 2);  // [256] (8B aligned region)

    const int t  = threadIdx.x;
    const int cg = t & 7;          // code group 0..7
    const int rg = t >> 3;         // row group 0..31
    const long base = (long)blockIdx.x * ROWS_CTA;

    // ---- stage z tile (threads 0..127, one row each) + z2 + all c2 ----
    if (t < ROWS_CTA) {
        const float4* a4 = (const float4*)(z + (base + t) * D);
        float s[32];
#pragma unroll
        for (int i4 = 0; i4 < D / 4; i4++) {
            float4 a = a4[i4];
            s_zp[(2 * i4 + 0) * ZP_STRIDE + t] = pack2(a.x, a.y);
            s_zp[(2 * i4 + 1) * ZP_STRIDE + t] = pack2(a.z, a.w);
            s[2 * i4 + 0] = a.x * a.x + a.y * a.y;
            s[2 * i4 + 1] = a.z * a.z + a.w * a.w;
        }
#pragma unroll
        for (int off = 16; off >= 1; off >>= 1)
#pragma unroll
            for (int i = 0; i < off; i++) s[i] = s[i] + s[i + off];
        s_z2[t] = s[0];
    }
#pragma unroll
    for (int i = t; i < K_CODES; i += THREADS) s_c2[i] = g_c2[i];
    __syncthreads();

    // z2 for this thread's 4 rows (read once)
    float zz[TR];
#pragma unroll
    for (int r = 0; r < TR; r++) zz[r] = s_z2[4 * rg + r];

    float mv[TR]; int mi[TR];
#pragma unroll
    for (int r = 0; r < TR; r++) { mv[r] = 3.402823466e38f; mi[r] = 0; }

    for (int ch = 0; ch < NCHUNK; ++ch) {
        __syncthreads();
        // stage codebook chunk as dim-pair u64s: s_cp[i][k]
        {
            const float4* src = (const float4*)(cb + (size_t)ch * CHUNK * D);
#pragma unroll
            for (int it = 0; it < CHUNK * (D / 4) / THREADS; it++) {
                int piece = it * THREADS + t;      // = k*16 + d4
                int k  = piece >> 4;
                int d4 = piece & 15;
                float4 v = src[piece];
                s_cp[(2 * d4 + 0) * CP_STRIDE + k] = pack2(v.x, v.y);
                s_cp[(2 * d4 + 1) * CP_STRIDE + k] = pack2(v.z, v.w);
            }
        }
        __syncthreads();

        for (int sub = 0; sub < CHUNK / (8 * TC); sub++) {
            const int kb = sub * 64 + cg * TC;     // code offset within chunk
            u64 acc[TR][TC];
#pragma unroll
            for (int r = 0; r < TR; r++)
#pragma unroll
                for (int j = 0; j < TC; j++) acc[r][j] = 0ull;

#pragma unroll 8
            for (int i = 0; i < NPAIR; i++) {
                const u64* zrow = s_zp + (size_t)i * ZP_STRIDE + 4 * rg;
                ulonglong2 za = *(const ulonglong2*)(zrow);
                ulonglong2 zb = *(const ulonglong2*)(zrow + 2);
                u64 zv[TR] = { za.x, za.y, zb.x, zb.y };
                const u64* crow = s_cp + (size_t)i * CP_STRIDE + kb;
                ulonglong2 c0 = *(const ulonglong2*)(crow);
                ulonglong2 c1 = *(const ulonglong2*)(crow + 2);
                ulonglong2 c2v = *(const ulonglong2*)(crow + 4);
                ulonglong2 c3 = *(const ulonglong2*)(crow + 6);
                u64 cv[TC] = { c0.x, c0.y, c1.x, c1.y, c2v.x, c2v.y, c3.x, c3.y };
#pragma unroll
                for (int r = 0; r < TR; r++)
#pragma unroll
                    for (int j = 0; j < TC; j++)
                        acc[r][j] = ffma2(zv[r], cv[j], acc[r][j]);
            }

            const int kglob = ch * CHUNK + kb;
#pragma unroll
            for (int j = 0; j < TC; j++) {
                float c2s = s_c2[kglob + j];
#pragma unroll
                for (int r = 0; r < TR; r++) {
                    float e, o; unpack2(acc[r][j], e, o);
                    float dv = fmaf(-2.0f, e + o, zz[r]) + c2s;  // 2*cross exact
                    if (dv < mv[r]) { mv[r] = dv; mi[r] = kglob + j; }
                }
            }
        }
    }

    // ---- cross-thread reduction over the 8 code-groups per row ----
    __syncthreads();   // mainloop smem reads done; safe to overlay s_cp
#pragma unroll
    for (int r = 0; r < TR; r++) {
        candv[(4 * rg + r) * 8 + cg] = mv[r];
        candi[(4 * rg + r) * 8 + cg] = mi[r];
    }
    __syncthreads();

    double lacc = 0.0;
    if (t < ROWS_CTA) {
        float bv = candv[t * 8 + 0];
        int   bi = candi[t * 8 + 0];
#pragma unroll
        for (int g = 1; g < 8; g++) {
            float v = candv[t * 8 + g];
            int   i = candi[t * 8 + g];
            if (v < bv || (v == bv && i < bi)) { bv = v; bi = i; }  // first-index tie-break
        }
        const long row = base + t;
        const float4* q = (const float4*)(cb + (size_t)bi * D);
        float4* o = (float4*)(out + row * D);
#pragma unroll
        for (int i4 = 0; i4 < D / 4; i4++) {
            float4 a = q[i4];
            float x, y, u, w, d;
            unpack2(s_zp[(2 * i4 + 0) * ZP_STRIDE + t], x, y);
            unpack2(s_zp[(2 * i4 + 1) * ZP_STRIDE + t], u, w);
            d = a.x - x; lacc += (double)(d * d);
            d = a.y - y; lacc += (double)(d * d);
            d = a.z - u; lacc += (double)(d * d);
            d = a.w - w; lacc += (double)(d * d);
            o[i4] = a;
        }
        if ((long)out_size >= (long)B * D + 1 + B)
            out[(long)B * D + 1 + row] = (float)bi;
    }

    // ---- block-reduce loss, last CTA finalizes ----
    __syncthreads();
    sd[t] = lacc;
    __syncthreads();
#pragma unroll
    for (int off = THREADS / 2; off >= 1; off >>= 1) {
        if (t < off) sd[t] += sd[t + off];
        __syncthreads();
    }
    if (t == 0) {
        atomicAdd(&g_loss, sd[0]);
        __threadfence();
        unsigned v = atomicAdd(&g_done, 1u);
        if (v == gridDim.x - 1) {
            g_done = 0u;
            if ((long)out_size >= (long)B * D + 1) {
                float m = (float)(g_loss / (double)((long)B * D));
                out[(size_t)B * D] = m + 0.25f * m;
            }
        }
    }
}

extern "C" void kernel_launch(void* const* d_in, const int* in_sizes, int n_in,
                              void* d_out, int out_size) {
    const float* z  = (const float*)d_in[0];
    const float* cb = (const float*)d_in[1];
    float* out = (float*)d_out;
    const int B = in_sizes[0] / D;

    const size_t smem = (size_t)NPAIR * ZP_STRIDE * 8 + (size_t)NPAIR * CP_STRIDE * 8
                      + K_CODES * 4 + ROWS_CTA * 4 + 64;
    cudaFuncSetAttribute(vq_main, cudaFuncAttributeMaxDynamicSharedMemorySize, (int)smem);

    vq_prep<<<K_CODES, D>>>(cb);
    vq_main<<<B / ROWS_CTA, THREADS, smem>>>(z, cb, out, B, out_size);
}

// round 8
// speedup vs baseline: 2.4005x; 2.4005x over previous
#include <cuda_runtime.h>

// VectorQuantizer: z [B,64] f32, codebook [1024,64] f32
// out = concat( z_q_st [B*64], vq_loss [1], indices-as-float [B] )

typedef unsigned long long u64;

#define K_CODES 1024
#define D 64
#define THREADS 256
#define ROWS_CTA 256               // 2 rows per lane-pair, 128 pairs per CTA
#define CHUNK 256                  // codes staged per pass
#define NCHUNK (K_CODES/CHUNK)
#define KB 4                       // codes per register tile

__device__ double   g_loss;
__device__ unsigned g_done;
__device__ float    g_c2[K_CODES];

static __device__ __forceinline__ void unpack2(u64 v, float& x, float& y) {
    asm("mov.b64 {%0,%1},%2;" : "=f"(x), "=f"(y) : "l"(v));
}
static __device__ __forceinline__ u64 ffma2(u64 a, u64 b, u64 c) {
    u64 d; asm("fma.rn.f32x2 %0,%1,%2,%3;" : "=l"(d) : "l"(a), "l"(b), "l"(c)); return d;
}

// Prep: c2 per code (pairwise tree, unchanged since R1), zero loss + done counter.
__global__ void vq_prep(const float* __restrict__ cb) {
    __shared__ float s[D];
    int k = blockIdx.x, d = threadIdx.x;
    float v = cb[k * D + d];
    s[d] = v * v;
    __syncthreads();
#pragma unroll
    for (int off = D / 2; off >= 1; off >>= 1) {
        if (d < off) s[d] = s[d] + s[d + off];
        __syncthreads();
    }
    if (d == 0) {
        g_c2[k] = s[0];
        if (k == 0) { g_loss = 0.0; g_done = 0u; }
    }
}

__global__ void __launch_bounds__(THREADS, 2)
vq_main(const float* __restrict__ z, const float* __restrict__ cb,
        float* __restrict__ out, int B, int out_size) {
    extern __shared__ char smraw[];
    float* s_c  = (float*)smraw;            // [CHUNK][64] codebook, halves 16B-interleaved
    float* s_c2 = s_c + CHUNK * D;          // [1024] all c2
    double* sd  = (double*)smraw;           // overlay for final loss reduce

    const int t    = threadIdx.x;
    const int lane = t & 31;
    const int w    = t >> 5;
    const int h    = lane >> 4;             // D-half: 0 -> dims 0..31, 1 -> 32..63
    const int s    = lane & 15;
    const long base = (long)blockIdx.x * ROWS_CTA;
    const long rA = base + ((long)w * 16 + s) * 2;
    const long rB = rA + 1;

    // Load this thread's half of rows A and B as u64 dim-pairs (pair j = dims h*32+2j, +1)
    u64 zA[16], zB[16];
    {
        const ulonglong2* pa = (const ulonglong2*)(z + rA * D + h * 32);
        const ulonglong2* pb = (const ulonglong2*)(z + rB * D + h * 32);
#pragma unroll
        for (int i = 0; i < 8; i++) {
            ulonglong2 va = pa[i]; zA[2 * i] = va.x; zA[2 * i + 1] = va.y;
            ulonglong2 vb = pb[i]; zB[2 * i] = vb.x; zB[2 * i + 1] = vb.y;
        }
    }

    // z2: EXACT R1 tree. Level 1 of the 32-leaf tree is s[j] + s[j+16], which is
    // exactly own-half pair-sum + other-half pair-sum -> one shfl per j (commutative
    // add => identical bits on both lanes), then tree(16) locally.
    float z2A, z2B;
    {
        float sa[16], sb[16];
#pragma unroll
        for (int i = 0; i < 16; i++) {
            float e, o;
            unpack2(zA[i], e, o); sa[i] = e * e + o * o;
            unpack2(zB[i], e, o); sb[i] = e * e + o * o;
        }
#pragma unroll
        for (int i = 0; i < 16; i++) {
            sa[i] = sa[i] + __shfl_xor_sync(0xffffffffu, sa[i], 16);
            sb[i] = sb[i] + __shfl_xor_sync(0xffffffffu, sb[i], 16);
        }
#pragma unroll
        for (int off = 8; off >= 1; off >>= 1)
#pragma unroll
            for (int i = 0; i < off; i++) { sa[i] = sa[i] + sa[i + off]; sb[i] = sb[i] + sb[i + off]; }
        z2A = sa[0];
        z2B = sb[0];
    }

    // stage all c2 once
#pragma unroll
    for (int i = t; i < K_CODES; i += THREADS) s_c2[i] = g_c2[i];

    float mvA = 3.402823466e38f, mvB = 3.402823466e38f;
    int   miA = 0, miB = 0;

    for (int ch = 0; ch < NCHUNK; ++ch) {
        __syncthreads();
        // Stage codebook chunk with halves interleaved at 16B granularity:
        // global 16B-chunk f (0..15) of a row -> smem chunk (f<8 ? 2f : 2(f-8)+1).
        // Main-loop read addr for (i,h) is chunk 2i+h -> banks 8i vs 8i+4: disjoint.
        {
            const float4* src = (const float4*)(cb + (size_t)ch * CHUNK * D);
#pragma unroll
            for (int it = 0; it < CHUNK * (D / 4) / THREADS; it++) {
                int piece = it * THREADS + t;
                int k = piece >> 4;
                int f = piece & 15;
                int dc = (f < 8) ? (2 * f) : (2 * (f - 8) + 1);
                *(float4*)(s_c + (size_t)k * D + dc * 4) = src[piece];
            }
        }
        __syncthreads();

        const int kbase = ch * CHUNK;
        for (int kb = 0; kb < CHUNK; kb += KB) {
            u64 accA[KB], accB[KB];
#pragma unroll
            for (int j = 0; j < KB; j++) { accA[j] = 0ull; accB[j] = 0ull; }

#pragma unroll
            for (int i = 0; i < 8; i++) {
                u64 z0A = zA[2 * i], z1A = zA[2 * i + 1];
                u64 z0B = zB[2 * i], z1B = zB[2 * i + 1];
#pragma unroll
                for (int j = 0; j < KB; j++) {
                    // 16B chunk (2i+h) of code row: 2 dim-pairs of this half
                    ulonglong2 c = *(const ulonglong2*)(s_c + (size_t)(kb + j) * D + (2 * i + h) * 4);
                    accA[j] = ffma2(z0A, c.x, accA[j]);
                    accA[j] = ffma2(z1A, c.y, accA[j]);
                    accB[j] = ffma2(z0B, c.x, accB[j]);
                    accB[j] = ffma2(z1B, c.y, accB[j]);
                }
            }

#pragma unroll
            for (int j = 0; j < KB; j++) {
                const int k = kbase + kb + j;
                const float c2s = s_c2[k];
                float e, o;
                unpack2(accA[j], e, o);
                float pA = e + o;
                float crossA = pA + __shfl_xor_sync(0xffffffffu, pA, 16);
                float dvA = fmaf(-2.0f, crossA, z2A) + c2s;   // 2*cross exact (x2 power of 2)
                if (dvA < mvA) { mvA = dvA; miA = k; }        // strict < => first index wins
                unpack2(accB[j], e, o);
                float pB = e + o;
                float crossB = pB + __shfl_xor_sync(0xffffffffu, pB, 16);
                float dvB = fmaf(-2.0f, crossB, z2B) + c2s;
                if (dvB < mvB) { mvB = dvB; miB = k; }
            }
        }
    }

    // Epilogue: each half-lane gathers/writes its own 32 dims of z_q, loss partial
    double lacc = 0.0;
    {
        const float4* qa = (const float4*)(cb + (size_t)miA * D + h * 32);
        const float4* qb = (const float4*)(cb + (size_t)miB * D + h * 32);
        float4* oa = (float4*)(out + rA * D + h * 32);
        float4* ob = (float4*)(out + rB * D + h * 32);
#pragma unroll
        for (int i = 0; i < 8; i++) {
            float4 a = qa[i];
            float x, y, u, v, d;
            unpack2(zA[2 * i],     x, y);
            unpack2(zA[2 * i + 1], u, v);
            d = a.x - x; lacc += (double)(d * d);
            d = a.y - y; lacc += (double)(d * d);
            d = a.z - u; lacc += (double)(d * d);
            d = a.w - v; lacc += (double)(d * d);
            oa[i] = a;
            float4 b = qb[i];
            unpack2(zB[2 * i],     x, y);
            unpack2(zB[2 * i + 1], u, v);
            d = b.x - x; lacc += (double)(d * d);
            d = b.y - y; lacc += (double)(d * d);
            d = b.z - u; lacc += (double)(d * d);
            d = b.w - v; lacc += (double)(d * d);
            ob[i] = b;
        }
    }

    if (h == 0 && (long)out_size >= (long)B * D + 1 + B) {
        const long iofs = (long)B * D + 1;
        out[iofs + rA] = (float)miA;
        out[iofs + rB] = (float)miB;
    }

    // block-reduce loss (overlay smem), last CTA finalizes
    __syncthreads();
    sd[t] = lacc;
    __syncthreads();
#pragma unroll
    for (int off = THREADS / 2; off >= 1; off >>= 1) {
        if (t < off) sd[t] += sd[t + off];
        __syncthreads();
    }
    if (t == 0) {
        atomicAdd(&g_loss, sd[0]);
        __threadfence();
        unsigned v = atomicAdd(&g_done, 1u);
        if (v == gridDim.x - 1) {
            g_done = 0u;
            if ((long)out_size >= (long)B * D + 1) {
                float m = (float)(g_loss / (double)((long)B * D));
                out[(size_t)B * D] = m + 0.25f * m;
            }
        }
    }
}

extern "C" void kernel_launch(void* const* d_in, const int* in_sizes, int n_in,
                              void* d_out, int out_size) {
    const float* z  = (const float*)d_in[0];
    const float* cb = (const float*)d_in[1];
    float* out = (float*)d_out;
    const int B = in_sizes[0] / D;

    const size_t smem = (size_t)CHUNK * D * sizeof(float) + K_CODES * sizeof(float);
    cudaFuncSetAttribute(vq_main, cudaFuncAttributeMaxDynamicSharedMemorySize, (int)smem);

    vq_prep<<<K_CODES, D>>>(cb);
    vq_main<<<B / ROWS_CTA, THREADS, smem>>>(z, cb, out, B, out_size);
}